// round 16
// baseline (speedup 1.0000x reference)
#include <cuda_runtime.h>
#include <stdint.h>

// Problem constants (fixed by the reference):
//   B=16, L=512, NSESS=4, S=512, H=512
// Logical inputs (identified by element count, order-invariant):
//   session_repre        (B,4,S,H) f32        -> 8,388,608 elems (unique)
//   state_transition_mat (B,L,5)   int64/int32 -> 40,960 elems (unique)
// Output: (B, L, 5, H) f32
//
// out[b,l,j,:] = session_repre[b, sess_idx[j], stm[b,l,j]-1, :]
//   with sess_idx = {3,0,1,2,3}
// out[b,l,0,:] = mean_{j=0..3} gathered[b,l,j,:]
//
// FINAL, CONVERGED (= R9; best measured: bench 21.76us, 32 regs, occ ~80%).
// Persistent single-wave grid (1184 CTAs = 148 SM x 8 blocks of 256 thr),
// 2 (b,l) groups per block, one float4 per thread per row.
//
// Campaign summary (14 measured variants, R2-R15):
//  - Kernel time data-path invariant at 19.5-21.2us: STG/stcs/TMA-store/
//    TMA-both/v8-evict-hints/.cg/multi-pair/persistent/prefetch/uniform-dist
//    all in-band -> latency-coupled LTS floor for the 168MB read+write
//    stream (reads L2-resident; DRAM traffic ~= the 84MB write stream).
//  - Bench = kernel + replay overhead; overhead shrinks with grid size
//    (8192 CTAs +5.2us, 4096 +3.1us, 1184 +1.0us) -> single-wave wins.
//  - Regs > ~36 drops occupancy a tier and always loses (prefetch 38r/60%,
//    .cg-asm 40r/61%, v8 48r/49%). __ldg/__stcs intrinsics keep 32 regs;
//    do not replace with inline asm.
//  - Run-to-run noise ±0.8us; 21.8-22.7 is one statistical band.

#define B_DIM 16
#define L_DIM 512
#define S_DIM 512
#define H_DIM 512
#define H4    (H_DIM / 4)        // 128 float4 per row
#define NPAIRS (B_DIM * L_DIM)   // 8192
#define GRID_CTAS (148 * 8)      // one full wave at 256 thr (2048 thr/SM)

__global__ void __launch_bounds__(256)
state_matrix_encoder_kernel(const float4* __restrict__ sess,
                            const int* __restrict__ stm32,
                            float4* __restrict__ out) {
    const int group0  = blockIdx.x * 2 + (threadIdx.x >> 7); // (b,l) group id
    const int ngroups = GRID_CTAS * 2;
    const int t       = threadIdx.x & 127;   // 0..127 (one float4 per row)

    // Index dtype detection from data: values are in [1,512] (nonzero).
    // int64 LE layout -> word[1] == high word of idx0 == 0.
    // int32 layout    -> word[1] == idx1 in [1,512] != 0.
    const bool idx64 = (__ldg(&stm32[1]) == 0);

    for (int bl = group0; bl < NPAIRS; bl += ngroups) {
        const int b = bl >> 9;               // / L_DIM

        int p0, p1, p2, p3, p4;
        if (idx64) {
            // int64 indices: 5*8B = 40B per (b,l), 8B-aligned.
            const int4 a = __ldg((const int4*)(stm32 + bl * 10));
            const int4 c = __ldg((const int4*)(stm32 + bl * 10 + 4));
            const int2 e = __ldg((const int2*)(stm32 + bl * 10 + 8));
            p0 = a.x - 1; p1 = a.z - 1; p2 = c.x - 1; p3 = c.z - 1; p4 = e.x - 1;
        } else {
            const int* q = stm32 + bl * 5;
            p0 = __ldg(&q[0]) - 1; p1 = __ldg(&q[1]) - 1; p2 = __ldg(&q[2]) - 1;
            p3 = __ldg(&q[3]) - 1; p4 = __ldg(&q[4]) - 1;
        }

        // session_repre row base (in rows): (b*4 + s)*S + pos.
        // All 5 gathers issue back-to-back (full MLP).
        const size_t bbase = (size_t)b * 4 * S_DIM;
        const float4 g0 = __ldg(&sess[(bbase + (size_t)3 * S_DIM + p0) * H4 + t]);
        const float4 g1 = __ldg(&sess[(bbase + (size_t)0 * S_DIM + p1) * H4 + t]);
        const float4 g2 = __ldg(&sess[(bbase + (size_t)1 * S_DIM + p2) * H4 + t]);
        const float4 g3 = __ldg(&sess[(bbase + (size_t)2 * S_DIM + p3) * H4 + t]);
        const float4 g4 = __ldg(&sess[(bbase + (size_t)3 * S_DIM + p4) * H4 + t]);

        float4 pooled;
        pooled.x = (g0.x + g1.x + g2.x + g3.x) * 0.25f;
        pooled.y = (g0.y + g1.y + g2.y + g3.y) * 0.25f;
        pooled.z = (g0.z + g1.z + g2.z + g3.z) * 0.25f;
        pooled.w = (g0.w + g1.w + g2.w + g3.w) * 0.25f;

        // Streaming (evict-first) stores: output is never re-read; keep the
        // 84MB write stream from displacing session_repre in L2.
        float4* o = out + (size_t)bl * 5 * H4;
        __stcs(o + 0 * H4 + t, pooled);
        __stcs(o + 1 * H4 + t, g1);
        __stcs(o + 2 * H4 + t, g2);
        __stcs(o + 3 * H4 + t, g3);
        __stcs(o + 4 * H4 + t, g4);
    }
}

extern "C" void kernel_launch(void* const* d_in, const int* in_sizes, int n_in,
                              void* d_out, int out_size) {
    // Order-invariant input identification by element count.
    const float4* sess  = nullptr;
    const int*    stm32 = nullptr;
    for (int i = 0; i < n_in; i++) {
        if (in_sizes[i] == B_DIM * 4 * S_DIM * H_DIM) sess  = (const float4*)d_in[i];
        else if (in_sizes[i] == B_DIM * L_DIM * 5)    stm32 = (const int*)d_in[i];
    }

    state_matrix_encoder_kernel<<<GRID_CTAS, 256>>>(sess, stm32, (float4*)d_out);
}

// round 17
// speedup vs baseline: 1.0620x; 1.0620x over previous
#include <cuda_runtime.h>
#include <stdint.h>

// Problem constants (fixed by the reference):
//   B=16, L=512, NSESS=4, S=512, H=512
// Logical inputs (identified by element count, order-invariant):
//   session_repre        (B,4,S,H) f32        -> 8,388,608 elems (unique)
//   state_transition_mat (B,L,5)   int64/int32 -> 40,960 elems (unique)
// Output: (B, L, 5, H) f32
//
// out[b,l,j,:] = session_repre[b, sess_idx[j], stm[b,l,j]-1, :]
//   with sess_idx = {3,0,1,2,3}
// out[b,l,0,:] = mean_{j=0..3} gathered[b,l,j,:]
//
// FINAL, CONVERGED (= R9; replicates: bench 21.76/22.56/22.59/23.01us,
// kernel 20.2-21.2us, 32 regs, occ ~80%). Persistent single-wave grid
// (1184 CTAs = 148 SM x 8 blocks of 256 thr), 2 (b,l) groups per block,
// one float4 per thread per row.
//
// Campaign summary (14 structural variants, R2-R16):
//  - Kernel time is data-path invariant at 19.5-21.2us: STG/stcs/TMA-store/
//    TMA-both/v8-evict-hints/.cg/multi-pair/persistent/prefetch/uniform-dist
//    all in-band -> latency-coupled LTS floor for the 168MB read+write
//    stream (reads L2-resident; DRAM traffic ~= the 84MB write stream).
//  - Bench = kernel + replay overhead; overhead shrinks with grid size
//    (8192 CTAs +5.2us, 4096 +3.1us, 1184 +1.0us) -> single-wave wins.
//  - Regs > ~36 drops occupancy a tier and always loses (prefetch 38r/60%,
//    .cg-asm 40r/61%, v8 48r/49%). __ldg/__stcs intrinsics keep 32 regs;
//    do not replace with inline asm.
//  - Residual bench spread (+-0.8us) is harness/replay noise: kernel-time
//    and bench-time rankings are uncorrelated across replicates.

#define B_DIM 16
#define L_DIM 512
#define S_DIM 512
#define H_DIM 512
#define H4    (H_DIM / 4)        // 128 float4 per row
#define NPAIRS (B_DIM * L_DIM)   // 8192
#define GRID_CTAS (148 * 8)      // one full wave at 256 thr (2048 thr/SM)

__global__ void __launch_bounds__(256)
state_matrix_encoder_kernel(const float4* __restrict__ sess,
                            const int* __restrict__ stm32,
                            float4* __restrict__ out) {
    const int group0  = blockIdx.x * 2 + (threadIdx.x >> 7); // (b,l) group id
    const int ngroups = GRID_CTAS * 2;
    const int t       = threadIdx.x & 127;   // 0..127 (one float4 per row)

    // Index dtype detection from data: values are in [1,512] (nonzero).
    // int64 LE layout -> word[1] == high word of idx0 == 0.
    // int32 layout    -> word[1] == idx1 in [1,512] != 0.
    const bool idx64 = (__ldg(&stm32[1]) == 0);

    for (int bl = group0; bl < NPAIRS; bl += ngroups) {
        const int b = bl >> 9;               // / L_DIM

        int p0, p1, p2, p3, p4;
        if (idx64) {
            // int64 indices: 5*8B = 40B per (b,l), 8B-aligned.
            const int4 a = __ldg((const int4*)(stm32 + bl * 10));
            const int4 c = __ldg((const int4*)(stm32 + bl * 10 + 4));
            const int2 e = __ldg((const int2*)(stm32 + bl * 10 + 8));
            p0 = a.x - 1; p1 = a.z - 1; p2 = c.x - 1; p3 = c.z - 1; p4 = e.x - 1;
        } else {
            const int* q = stm32 + bl * 5;
            p0 = __ldg(&q[0]) - 1; p1 = __ldg(&q[1]) - 1; p2 = __ldg(&q[2]) - 1;
            p3 = __ldg(&q[3]) - 1; p4 = __ldg(&q[4]) - 1;
        }

        // session_repre row base (in rows): (b*4 + s)*S + pos.
        // All 5 gathers issue back-to-back (full MLP).
        const size_t bbase = (size_t)b * 4 * S_DIM;
        const float4 g0 = __ldg(&sess[(bbase + (size_t)3 * S_DIM + p0) * H4 + t]);
        const float4 g1 = __ldg(&sess[(bbase + (size_t)0 * S_DIM + p1) * H4 + t]);
        const float4 g2 = __ldg(&sess[(bbase + (size_t)1 * S_DIM + p2) * H4 + t]);
        const float4 g3 = __ldg(&sess[(bbase + (size_t)2 * S_DIM + p3) * H4 + t]);
        const float4 g4 = __ldg(&sess[(bbase + (size_t)3 * S_DIM + p4) * H4 + t]);

        float4 pooled;
        pooled.x = (g0.x + g1.x + g2.x + g3.x) * 0.25f;
        pooled.y = (g0.y + g1.y + g2.y + g3.y) * 0.25f;
        pooled.z = (g0.z + g1.z + g2.z + g3.z) * 0.25f;
        pooled.w = (g0.w + g1.w + g2.w + g3.w) * 0.25f;

        // Streaming (evict-first) stores: output is never re-read; keep the
        // 84MB write stream from displacing session_repre in L2.
        float4* o = out + (size_t)bl * 5 * H4;
        __stcs(o + 0 * H4 + t, pooled);
        __stcs(o + 1 * H4 + t, g1);
        __stcs(o + 2 * H4 + t, g2);
        __stcs(o + 3 * H4 + t, g3);
        __stcs(o + 4 * H4 + t, g4);
    }
}

extern "C" void kernel_launch(void* const* d_in, const int* in_sizes, int n_in,
                              void* d_out, int out_size) {
    // Order-invariant input identification by element count.
    const float4* sess  = nullptr;
    const int*    stm32 = nullptr;
    for (int i = 0; i < n_in; i++) {
        if (in_sizes[i] == B_DIM * 4 * S_DIM * H_DIM) sess  = (const float4*)d_in[i];
        else if (in_sizes[i] == B_DIM * L_DIM * 5)    stm32 = (const int*)d_in[i];
    }

    state_matrix_encoder_kernel<<<GRID_CTAS, 256>>>(sess, stm32, (float4*)d_out);
}